// round 12
// baseline (speedup 1.0000x reference)
#include <cuda_runtime.h>
#include <cuda_fp16.h>
#include <cstdint>

// ============================================================
// ShiftConv (sm_103 non-'a' target): HMMA mma.sync fp16 GEMM.
// out[b,o,h,w] = bias[o] + sum_s sum_c W[o, s*192+c] * x[b,c,h+dh,w+dw]
// GEMM: C[pix, 192] = A[pix, 960] * W^T.
// R12: grouped mixed-precision accumulation — HMMA with fp16 C/D (the
// 2x-rate mma.sync path) over K-groups of 64, promoted into persistent
// fp32 accumulators every 2 k-iters. Warp tile 64x32, CTA M128xN64,
// 3 CTAs/SM. A via cp.async+ldmatrix, B fragment-major LDG.128.
// ============================================================

#define BATCH 4
#define CCH   192
#define HDIM  256
#define WDIM  256
#define HP    258
#define WP    258
#define OCH   192
#define KTOT  (5 * CCH)   // 960

static constexpr int XPAD_ELEMS = BATCH * HP * WP * CCH;

__device__ __align__(16) __half g_xh[XPAD_ELEMS];
// Fragment-major W: index = o*960 + it*32 + p*8 (halfs); 8 halfs cover
// k = it*32 + {2p,2p+1, 2p+8,2p+9, 2p+16,2p+17, 2p+24,2p+25}
__device__ __align__(16) __half g_wf[OCH * KTOT];

// ---------------- helpers ----------------

__device__ __forceinline__ uint32_t smem_to_u32(const void* p) {
    uint32_t a;
    asm("{ .reg .u64 t; cvta.to.shared.u64 t, %1; cvt.u32.u64 %0, t; }"
        : "=r"(a) : "l"(p));
    return a;
}

__device__ __forceinline__ void cp_async16(uint32_t saddr, const void* gaddr) {
    asm volatile("cp.async.cg.shared.global [%0], [%1], 16;"
                 :: "r"(saddr), "l"(gaddr));
}
#define CP_COMMIT() asm volatile("cp.async.commit_group;" ::: "memory")
#define CP_WAIT2()  asm volatile("cp.async.wait_group 2;" ::: "memory")

__device__ __forceinline__ void ldsm4(uint32_t* r, uint32_t addr) {
    asm volatile("ldmatrix.sync.aligned.m8n8.x4.shared.b16 {%0,%1,%2,%3}, [%4];"
                 : "=r"(r[0]), "=r"(r[1]), "=r"(r[2]), "=r"(r[3]) : "r"(addr));
}

// fp16-accumulate HMMA (2x rate path): D,C are 2x .f16x2 regs.
__device__ __forceinline__ void mma16816_f16(uint32_t* c, const uint32_t* a,
                                             uint32_t b0, uint32_t b1) {
    asm volatile(
        "mma.sync.aligned.m16n8k16.row.col.f16.f16.f16.f16 "
        "{%0,%1}, {%2,%3,%4,%5}, {%6,%7}, {%0,%1};"
        : "+r"(c[0]), "+r"(c[1])
        : "r"(a[0]), "r"(a[1]), "r"(a[2]), "r"(a[3]), "r"(b0), "r"(b1));
}

// ---------------- prep kernels ----------------

__global__ void prep_border() {
    const int per_b = 4 * WP * CCH;
    int i = blockIdx.x * blockDim.x + threadIdx.x;
    if (i >= BATCH * per_b) return;
    int b = i / per_b;
    int r = i % per_b;
    int line = r / (WP * CCH);
    int j = r % (WP * CCH);
    int pos = j / CCH;
    int c = j % CCH;
    int hh, ww;
    if      (line == 0) { hh = 0;      ww = pos; }
    else if (line == 1) { hh = HP - 1; ww = pos; }
    else if (line == 2) { hh = pos;    ww = 0;   }
    else                { hh = pos;    ww = WP - 1; }
    g_xh[(((size_t)b * HP + hh) * WP + ww) * CCH + c] = __float2half(0.0f);
}

// Transpose [B,C,H,W] fp32 -> padded pixel-major [B,HP,WP,C] fp16.
__global__ void prep_x(const float* __restrict__ x) {
    __shared__ float tile[32][129];
    int w0 = blockIdx.x * 128;
    int c0 = blockIdx.y * 32;
    int bh = blockIdx.z;
    int b = bh >> 8, h = bh & 255;
    int tid = threadIdx.x;           // 256
    int tx = tid & 31;
    int ty = tid >> 5;

#pragma unroll
    for (int i = 0; i < 4; i++) {
        int c = c0 + ty + i * 8;
        float4 v = *reinterpret_cast<const float4*>(
            x + (((size_t)b * CCH + c) * HDIM + h) * WDIM + w0 + tx * 4);
        tile[ty + i * 8][tx * 4 + 0] = v.x;
        tile[ty + i * 8][tx * 4 + 1] = v.y;
        tile[ty + i * 8][tx * 4 + 2] = v.z;
        tile[ty + i * 8][tx * 4 + 3] = v.w;
    }
    __syncthreads();

#pragma unroll
    for (int j = 0; j < 4; j++) {
        int idx = tid + j * 256;
        int w  = idx >> 3;
        int cq = (idx & 7) * 4;
        __half2 p0 = __floats2half2_rn(tile[cq + 0][w], tile[cq + 1][w]);
        __half2 p1 = __floats2half2_rn(tile[cq + 2][w], tile[cq + 3][w]);
        size_t dst = (((size_t)b * HP + (h + 1)) * WP + (w0 + w + 1)) * CCH
                     + c0 + cq;
        uint2 v;
        v.x = *reinterpret_cast<uint32_t*>(&p0);
        v.y = *reinterpret_cast<uint32_t*>(&p1);
        *reinterpret_cast<uint2*>(g_xh + dst) = v;
    }
}

// Pack W fp32 [o,k] into fragment-major fp16 g_wf.
__global__ void prep_w(const float* __restrict__ W) {
    int i = blockIdx.x * blockDim.x + threadIdx.x;   // 192*30*4 = 23040
    if (i >= OCH * 30 * 4) return;
    int p  = i & 3;
    int it = (i >> 2) % 30;
    int o  = i / 120;
    const float* src = W + (size_t)o * KTOT + it * 32 + p * 2;
    __half v[8];
#pragma unroll
    for (int q = 0; q < 4; q++) {
        v[q * 2]     = __float2half(src[q * 8]);
        v[q * 2 + 1] = __float2half(src[q * 8 + 1]);
    }
    *reinterpret_cast<uint4*>(g_wf + (size_t)o * KTOT + it * 32 + p * 8) =
        *reinterpret_cast<uint4*>(v);
}

// ---------------- main GEMM kernel ----------------
// CTA tile M=128 x N=64, K=960, k-step 32, 4-stage cp.async for A.
// 128 thr = 4 warps 2(M)x2(N); warp tile 64x32 (4 mi x 4 n8-tiles).
// fp16 group accumulators over K=64 groups, promoted to fp32.

static constexpr int STAGES   = 4;
static constexpr int A_ROWB   = 80;                 // 40 halfs (32 + 8 pad)
static constexpr int A_SZ     = 128 * A_ROWB;       // 10240 B / stage
static constexpr int SMEM_TOT = STAGES * A_SZ;      // 40960
static constexpr int KITERS   = 30;
static constexpr int NGROUPS  = 15;                 // 2 iters (K=64) each

__global__ __launch_bounds__(128, 3)
void shiftconv_gemm(const float* __restrict__ bias, float* __restrict__ out) {
    extern __shared__ char smem[];
    uint32_t sb = smem_to_u32(smem);

    int tid = threadIdx.x;
    int wid = tid >> 5;
    int lane = tid & 31;
    int wm = wid >> 1;         // 0..1  (M group of 64)
    int wn = wid & 1;          // 0..1  (N group of 32)

    int lm  = lane >> 3;       // ldmatrix matrix index 0..3
    int lr8 = lane & 7;
    int rowoff = (lm & 1) * 8 + lr8;
    int coloff = (lm >> 1) * 8;    // halfs

    int tile = blockIdx.x;                 // 0..6143
    int w0 = (tile & 1) * 128;
    int h  = (tile >> 1) & 255;
    int b  = (tile >> 9) & 3;
    int nt = tile >> 11;                   // 0..2 (N third) SLOWEST
    int o0 = nt * 64;

    // ---- A fill: one base ptr + int32 per-segment offsets ----
    int ar = tid;                          // pixel row 0..127
    uint32_t aoff[5];
#pragma unroll
    for (int s = 0; s < 5; s++) {
        int dh = (s == 3) - (s == 4);
        int dw = (s == 1) - (s == 2);
        aoff[s] = (uint32_t)((((b * HP) + (h + 1 + dh)) * WP
                              + (w0 + ar + 1 + dw)) * CCH);
    }
    uint32_t a_smem = sb + ar * A_ROWB;

    // ---- B fragment base pointer (per lane); n8-tile t at +t*8*KTOT ----
    const __half* wf0 = g_wf + (size_t)(o0 + wn * 32 + (lane >> 2)) * KTOT
                        + (lane & 3) * 8;

    float acc[4][4][4] = {};          // [mi][n8-tile][quad] fp32 main
    uint32_t hc[4][4][2];             // [mi][n8-tile][2] fp16x2 group acc
#pragma unroll
    for (int mi = 0; mi < 4; mi++)
#pragma unroll
        for (int t = 0; t < 4; t++) { hc[mi][t][0] = 0; hc[mi][t][1] = 0; }

    auto issueA = [&](int it) {
        int seg = (it * 43691) >> 18;      // it/6 for it<30
        int c0 = (it - seg * 6) * 32;
        const char* ga = reinterpret_cast<const char*>(g_xh + aoff[seg] + c0);
        uint32_t sa = a_smem + (it & 3) * A_SZ;
#pragma unroll
        for (int j = 0; j < 4; j++)
            cp_async16(sa + j * 16, ga + j * 16);
    };

#pragma unroll
    for (int s = 0; s < STAGES - 1; s++) { issueA(s); CP_COMMIT(); }

#pragma unroll 1
    for (int g = 0; g < NGROUPS; ++g) {
#pragma unroll
        for (int u = 0; u < 2; ++u) {
            int it = g * 2 + u;
            // B fragments: 4 x LDG.128 (one per n8-tile), before the wait.
            uint32_t bf[4][4];
#pragma unroll
            for (int t = 0; t < 4; t++) {
                const uint4* pB = reinterpret_cast<const uint4*>(
                    wf0 + (size_t)(t * 8) * KTOT + it * 32);
                uint4 v = __ldg(pB);
                bf[t][0] = v.x; bf[t][1] = v.y;
                bf[t][2] = v.z; bf[t][3] = v.w;
            }

            CP_WAIT2();
            __syncthreads();

            if (it + STAGES - 1 < KITERS) issueA(it + STAGES - 1);
            CP_COMMIT();

            uint32_t Ab = sb + (it & 3) * A_SZ;

#pragma unroll
            for (int kk = 0; kk < 2; kk++) {
#pragma unroll
                for (int mh = 0; mh < 2; mh++) {
                    uint32_t afr[2][4];
#pragma unroll
                    for (int m2 = 0; m2 < 2; m2++) {
                        int row = wm * 64 + (mh * 2 + m2) * 16 + rowoff;
                        int col = kk * 16 + coloff;
                        ldsm4(afr[m2], Ab + row * A_ROWB + col * 2);
                    }
#pragma unroll
                    for (int m2 = 0; m2 < 2; m2++) {
                        int mi = mh * 2 + m2;
#pragma unroll
                        for (int t = 0; t < 4; t++)
                            mma16816_f16(hc[mi][t], afr[m2],
                                         bf[t][kk * 2], bf[t][kk * 2 + 1]);
                    }
                }
            }
        }

        // ---- group end: promote fp16 group acc into fp32, re-zero ----
#pragma unroll
        for (int mi = 0; mi < 4; mi++)
#pragma unroll
            for (int t = 0; t < 4; t++) {
                __half2 h0 = *reinterpret_cast<__half2*>(&hc[mi][t][0]);
                __half2 h1 = *reinterpret_cast<__half2*>(&hc[mi][t][1]);
                float2 f0 = __half22float2(h0);
                float2 f1 = __half22float2(h1);
                acc[mi][t][0] += f0.x;
                acc[mi][t][1] += f0.y;
                acc[mi][t][2] += f1.x;
                acc[mi][t][3] += f1.y;
                hc[mi][t][0] = 0;
                hc[mi][t][1] = 0;
            }
    }

    // ---- epilogue: direct STG (8 consecutive pixels x 4B per store row) ----
    int g8 = lane >> 2;       // 0..7 pixel sub-row
    int q  = lane & 3;        // o pair selector
    size_t out_hw = (size_t)h * WDIM + w0;
#pragma unroll
    for (int mi = 0; mi < 4; mi++) {
        int r0 = wm * 64 + mi * 16 + g8;
#pragma unroll
        for (int t = 0; t < 4; t++) {
            int o = o0 + wn * 32 + t * 8 + 2 * q;
            float bz0 = __ldg(bias + o);
            float bz1 = __ldg(bias + o + 1);
            float* p0 = out + ((size_t)(b * OCH + o)) * (HDIM * WDIM)
                        + out_hw;
            float* p1 = p0 + (size_t)(HDIM * WDIM);
            p0[r0]     = acc[mi][t][0] + bz0;
            p1[r0]     = acc[mi][t][1] + bz1;
            p0[r0 + 8] = acc[mi][t][2] + bz0;
            p1[r0 + 8] = acc[mi][t][3] + bz1;
        }
    }
}

// ---------------- launch ----------------

extern "C" void kernel_launch(void* const* d_in, const int* in_sizes, int n_in,
                              void* d_out, int out_size) {
    const float* x = (const float*)d_in[0];    // [4,192,256,256]
    const float* W = (const float*)d_in[1];    // [192, 960]
    const float* bias = (const float*)d_in[2]; // [192]
    float* out = (float*)d_out;

    {
        int n = BATCH * 4 * WP * CCH;
        prep_border<<<(n + 255) / 256, 256>>>();
    }
    prep_x<<<dim3(WDIM / 128, CCH / 32, BATCH * HDIM), 256>>>(x);
    {
        int n = OCH * 30 * 4;
        prep_w<<<(n + 255) / 256, 256>>>(W);
    }
    cudaFuncSetAttribute(shiftconv_gemm,
                         cudaFuncAttributeMaxDynamicSharedMemorySize, SMEM_TOT);
    shiftconv_gemm<<<BATCH * HDIM * 2 * 3, 128, SMEM_TOT>>>(bias, out);
}

// round 13
// speedup vs baseline: 1.2613x; 1.2613x over previous
#include <cuda_runtime.h>
#include <cuda_fp16.h>
#include <cstdint>

// ============================================================
// ShiftConv (sm_103 non-'a' target): HMMA mma.sync fp16 GEMM.
// out[b,o,h,w] = bias[o] + sum_s sum_c W[o, s*192+c] * x[b,c,h+dh,w+dw]
// GEMM: C[pix, 192] = A[pix, 960] * W^T.
// R13: prep_x ELIMINATED — the GEMM's A-path loads raw fp32 x rows
// (with +-1 pixel halo, cp.async zfill at boundaries) into a 2-stage
// fp32 XBUF, converts in-kernel to the 80B-row fp16 A tile (bit-identical
// values to the old g_xh), then the proven R10 LDSM+HMMA path (which sits
// AT the HMMA.16816.F32 issue roofline, 0.25/cyc/SM). B = fragment-major
// W via LDG.128. CTA M128xN96, warp 64x48, 128 thr, 3 CTAs/SM.
// ============================================================

#define BATCH 4
#define CCH   192
#define HDIM  256
#define WDIM  256
#define OCH   192
#define KTOT  (5 * CCH)   // 960

// Fragment-major W: index = o*960 + it*32 + p*8 (halfs); 8 halfs cover
// k = it*32 + {2p,2p+1, 2p+8,2p+9, 2p+16,2p+17, 2p+24,2p+25}
__device__ __align__(16) __half g_wf[OCH * KTOT];

// ---------------- helpers ----------------

__device__ __forceinline__ uint32_t smem_to_u32(const void* p) {
    uint32_t a;
    asm("{ .reg .u64 t; cvta.to.shared.u64 t, %1; cvt.u32.u64 %0, t; }"
        : "=r"(a) : "l"(p));
    return a;
}

__device__ __forceinline__ void cp_async16z(uint32_t saddr, const void* gaddr,
                                            unsigned sz) {
    asm volatile("cp.async.cg.shared.global [%0], [%1], 16, %2;"
                 :: "r"(saddr), "l"(gaddr), "r"(sz));
}
#define CP_COMMIT() asm volatile("cp.async.commit_group;" ::: "memory")
#define CP_WAIT1()  asm volatile("cp.async.wait_group 1;" ::: "memory")

__device__ __forceinline__ void ldsm4(uint32_t* r, uint32_t addr) {
    asm volatile("ldmatrix.sync.aligned.m8n8.x4.shared.b16 {%0,%1,%2,%3}, [%4];"
                 : "=r"(r[0]), "=r"(r[1]), "=r"(r[2]), "=r"(r[3]) : "r"(addr));
}

__device__ __forceinline__ float lds_f32(uint32_t addr) {
    float f;
    asm volatile("ld.shared.f32 %0, [%1];" : "=f"(f) : "r"(addr));
    return f;
}

__device__ __forceinline__ void sts128(uint32_t addr, uint32_t a, uint32_t b,
                                       uint32_t c, uint32_t d) {
    asm volatile("st.shared.v4.b32 [%0], {%1,%2,%3,%4};"
                 :: "r"(addr), "r"(a), "r"(b), "r"(c), "r"(d) : "memory");
}

__device__ __forceinline__ void mma16816(float* c, const uint32_t* a,
                                         uint32_t b0, uint32_t b1) {
    asm volatile(
        "mma.sync.aligned.m16n8k16.row.col.f32.f16.f16.f32 "
        "{%0,%1,%2,%3}, {%4,%5,%6,%7}, {%8,%9}, {%0,%1,%2,%3};"
        : "+f"(c[0]), "+f"(c[1]), "+f"(c[2]), "+f"(c[3])
        : "r"(a[0]), "r"(a[1]), "r"(a[2]), "r"(a[3]), "r"(b0), "r"(b1));
}

// ---------------- prep kernel (W only) ----------------

__global__ void prep_w(const float* __restrict__ W) {
    int i = blockIdx.x * blockDim.x + threadIdx.x;   // 192*30*4 = 23040
    if (i >= OCH * 30 * 4) return;
    int p  = i & 3;
    int it = (i >> 2) % 30;
    int o  = i / 120;
    const float* src = W + (size_t)o * KTOT + it * 32 + p * 2;
    __half v[8];
#pragma unroll
    for (int q = 0; q < 4; q++) {
        v[q * 2]     = __float2half(src[q * 8]);
        v[q * 2 + 1] = __float2half(src[q * 8 + 1]);
    }
    *reinterpret_cast<uint4*>(g_wf + (size_t)o * KTOT + it * 32 + p * 8) =
        *reinterpret_cast<uint4*>(v);
}

// ---------------- fused GEMM kernel ----------------
// CTA tile M=128 x N=96, K=960, k-step 32. 128 thr = 4 warps 2(M)x2(N);
// warp tile 64x48. 3 CTAs/SM.
// Smem: AF16 2 stages x 10240B (128 rows x 80B), XBUF 2 stages x 18432B
// (32 c-rows x 144 fp32, 576B row stride).

static constexpr int A_ROWB   = 80;
static constexpr int AF_SZ    = 128 * A_ROWB;       // 10240
static constexpr int X_OFF    = 2 * AF_SZ;          // 20480
static constexpr int X_ROWB   = 576;                // 144 floats
static constexpr int X_SZ     = 32 * X_ROWB;        // 18432
static constexpr int SMEM_TOT = X_OFF + 2 * X_SZ;   // 57344
static constexpr int KITERS   = 30;

__global__ __launch_bounds__(128, 3)
void shiftconv_gemm(const float* __restrict__ x,
                    const float* __restrict__ bias,
                    float* __restrict__ out) {
    extern __shared__ char smem[];
    uint32_t sb = smem_to_u32(smem);

    int tid = threadIdx.x;
    int wid = tid >> 5;
    int lane = tid & 31;
    int wm = wid >> 1;         // 0..1  (M group of 64)
    int wn = wid & 1;          // 0..1  (N group of 48)

    int lm  = lane >> 3;       // ldmatrix matrix index 0..3
    int lr8 = lane & 7;
    int rowoff = (lm & 1) * 8 + lr8;
    int coloff = (lm >> 1) * 8;    // halfs

    int tile = blockIdx.x;                 // 0..4095
    int w0 = (tile & 1) * 128;
    int h  = (tile >> 1) & 255;
    int b  = (tile >> 9) & 3;
    int nh = tile >> 11;                   // N half SLOWEST -> W locality
    int o0 = nh * 96;

    const char* xb = reinterpret_cast<const char*>(x);

    // ---- B fragment base pointer (per lane) ----
    const __half* wf0 = g_wf + (size_t)(o0 + wn * 48 + (lane >> 2)) * KTOT
                        + (lane & 3) * 8;

    float acc[4][3][2][4] = {};

    // ---- XBUF fill for k-iter j: 32 c-rows x 36 16B-chunks, 9/thread ----
    // chunk id = tid + j2*128; row = id/36; col16 = id%36.
    // global float = ((b*192 + c0 + row)*256 + hs)*256 + (w0-4) + col16*4
    auto issueX = [&](int j) {
        int seg = (j * 43691) >> 18;       // j/6 for j<30
        int c0 = (j - seg * 6) * 32;
        int dh = (seg == 3) - (seg == 4);
        int hs = h + dh;
        bool rv = (hs >= 0) && (hs < HDIM);
        int hsc = rv ? hs : h;             // clamped (zfilled anyway)
        int base = (((b * CCH + c0) * HDIM + hsc) * WDIM + (w0 - 4)) * 4;
        uint32_t xd = sb + X_OFF + (j & 1) * X_SZ;
#pragma unroll
        for (int j2 = 0; j2 < 9; j2++) {
            int id = tid + j2 * 128;
            int row = id / 36;
            int col16 = id - row * 36;
            bool cv = !((w0 == 0 && col16 == 0) ||
                        (w0 == 128 && col16 >= 33));
            unsigned sz = (rv && cv) ? 16u : 0u;
            int off = base + row * (HDIM * WDIM * 4) + col16 * 16;
            cp_async16z(xd + row * X_ROWB + col16 * 16, xb + off, sz);
        }
    };

    // prologue: fills for iters 0 and 1
    issueX(0); CP_COMMIT();
    issueX(1); CP_COMMIT();

#pragma unroll 1
    for (int it = 0; it < KITERS; ++it) {
        // B fragments for this iter: 6 x LDG.128, issued before the wait.
        uint32_t bf[3][2][4];
#pragma unroll
        for (int nj = 0; nj < 3; nj++)
#pragma unroll
            for (int hf = 0; hf < 2; hf++) {
                const uint4* pB = reinterpret_cast<const uint4*>(
                    wf0 + (size_t)(nj * 16 + hf * 8) * KTOT + it * 32);
                uint4 v = __ldg(pB);
                bf[nj][hf][0] = v.x; bf[nj][hf][1] = v.y;
                bf[nj][hf][2] = v.z; bf[nj][hf][3] = v.w;
            }

        CP_WAIT1();
        __syncthreads();   // XBUF[it&1] ready; AF16[it&1] free (read it-2)

        // ---- convert XBUF[it&1] fp32 -> AF16[it&1] fp16 ----
        // thread t = pixel row; float index f = t + 4 + dw.
        {
            int seg = (it * 43691) >> 18;
            int dw = (seg == 1) - (seg == 2);
            uint32_t xs = sb + X_OFF + (it & 1) * X_SZ + (tid + 4 + dw) * 4;
            uint32_t ad = sb + (it & 1) * AF_SZ + tid * A_ROWB;
#pragma unroll
            for (int half_ = 0; half_ < 2; half_++) {
                uint32_t h2[8];
#pragma unroll
                for (int c2 = 0; c2 < 8; c2++) {
                    int c = half_ * 16 + c2 * 2;
                    float f0 = lds_f32(xs + c * X_ROWB);
                    float f1 = lds_f32(xs + (c + 1) * X_ROWB);
                    __half2 p = __floats2half2_rn(f0, f1);
                    h2[c2] = *reinterpret_cast<uint32_t*>(&p);
                }
                sts128(ad + half_ * 32,      h2[0], h2[1], h2[2], h2[3]);
                sts128(ad + half_ * 32 + 16, h2[4], h2[5], h2[6], h2[7]);
            }
        }
        __syncthreads();   // AF16[it&1] ready; XBUF[it&1] fully consumed

        if (it + 2 < KITERS) { issueX(it + 2); CP_COMMIT(); }

        uint32_t Ab = sb + (it & 1) * AF_SZ;

#pragma unroll
        for (int kk = 0; kk < 2; kk++) {
#pragma unroll
            for (int mh = 0; mh < 2; mh++) {
                uint32_t afr[2][4];
#pragma unroll
                for (int m2 = 0; m2 < 2; m2++) {
                    int row = wm * 64 + (mh * 2 + m2) * 16 + rowoff;
                    int col = kk * 16 + coloff;
                    ldsm4(afr[m2], Ab + row * A_ROWB + col * 2);
                }
#pragma unroll
                for (int m2 = 0; m2 < 2; m2++) {
                    int mi = mh * 2 + m2;
#pragma unroll
                    for (int nj = 0; nj < 3; nj++) {
                        mma16816(acc[mi][nj][0], afr[m2],
                                 bf[nj][0][kk * 2], bf[nj][0][kk * 2 + 1]);
                        mma16816(acc[mi][nj][1], afr[m2],
                                 bf[nj][1][kk * 2], bf[nj][1][kk * 2 + 1]);
                    }
                }
            }
        }
    }

    // ---- epilogue: direct STG (8 consecutive pixels x 4B per store row) ----
    int g8 = lane >> 2;
    int q  = lane & 3;
    size_t out_hw = (size_t)h * WDIM + w0;
#pragma unroll
    for (int mi = 0; mi < 4; mi++) {
        int r0 = wm * 64 + mi * 16 + g8;
#pragma unroll
        for (int nj = 0; nj < 3; nj++)
#pragma unroll
            for (int hf = 0; hf < 2; hf++) {
                int o = o0 + wn * 48 + nj * 16 + hf * 8 + 2 * q;
                float bz0 = __ldg(bias + o);
                float bz1 = __ldg(bias + o + 1);
                float* p0 = out + ((size_t)(b * OCH + o)) * (HDIM * WDIM)
                            + out_hw;
                float* p1 = p0 + (size_t)(HDIM * WDIM);
                p0[r0]     = acc[mi][nj][hf][0] + bz0;
                p1[r0]     = acc[mi][nj][hf][1] + bz1;
                p0[r0 + 8] = acc[mi][nj][hf][2] + bz0;
                p1[r0 + 8] = acc[mi][nj][hf][3] + bz1;
            }
    }
}

// ---------------- launch ----------------

extern "C" void kernel_launch(void* const* d_in, const int* in_sizes, int n_in,
                              void* d_out, int out_size) {
    const float* x = (const float*)d_in[0];    // [4,192,256,256]
    const float* W = (const float*)d_in[1];    // [192, 960]
    const float* bias = (const float*)d_in[2]; // [192]
    float* out = (float*)d_out;

    {
        int n = OCH * 30 * 4;
        prep_w<<<(n + 255) / 256, 256>>>(W);
    }
    cudaFuncSetAttribute(shiftconv_gemm,
                         cudaFuncAttributeMaxDynamicSharedMemorySize, SMEM_TOT);
    shiftconv_gemm<<<BATCH * HDIM * 2 * 2, 128, SMEM_TOT>>>(x, bias, out);
}